// round 5
// baseline (speedup 1.0000x reference)
#include <cuda_runtime.h>
#include <cuda_bf16.h>
#include <cstdint>

// ---------------------------------------------------------------------------
// Problem constants
//   B=8, T=2048, C=1024, NHEADS=16, HSIZE=64, N_GROUPS=8, group_t=256
//   qkv = x @ W_attn            [16384 x 3072], K=1024
//   per (b,h,g): causal attn over 257 tokens (256 + mean token), d=64
//   second attn over 7 groups (mean tokens), d=64
//   out = xo @ W_proj           [16384 x 1024], K=1024
// Outputs packed: out (16777216) | yq (57344) | yk (57344) | yv (57344)
// ---------------------------------------------------------------------------

#define MTOT   16384          // B*T
#define CDIM   1024
#define QKVN   3072
#define GT     256
#define LSEQ   257
#define LSTR   65             // padded smem row stride (conflict-free)
#define NBHG   1024           // 8*16*8
#define NMEAN  65536          // 8*16*8*64

__device__ float g_qkv[(size_t)MTOT * QKVN];   // 192 MB
__device__ float g_xo [(size_t)MTOT * CDIM];   //  64 MB
__device__ float g_qm [NMEAN];
__device__ float g_km [NMEAN];
__device__ float g_vm [NMEAN];
__device__ float g_xm [NMEAN];                 // attn output at mean-token rows

// ---------------------------------------------------------------------------
// SGEMM: C[M,N] = A[M,K] @ B[K,N], fp32, 128x128 block tile, 8x8 per thread.
// M%128==0, N%128==0, K%16==0 (holds for both GEMMs here).
// ---------------------------------------------------------------------------
__global__ __launch_bounds__(256, 2)
void sgemm128(const float* __restrict__ A, const float* __restrict__ B,
              float* __restrict__ C, int M, int N, int K)
{
    __shared__ float As[16][128];
    __shared__ float Bs[16][128];

    const int tid = threadIdx.x;
    const int tx  = tid & 15;
    const int ty  = tid >> 4;
    const int row0 = blockIdx.y * 128;
    const int col0 = blockIdx.x * 128;

    const float* Aptr = A + (size_t)row0 * K;
    const float* Bptr = B + col0;

    float acc[8][8];
#pragma unroll
    for (int i = 0; i < 8; i++)
#pragma unroll
        for (int j = 0; j < 8; j++) acc[i][j] = 0.f;

    for (int k0 = 0; k0 < K; k0 += 16) {
        // A tile: 128 rows x 16 k, as 512 float4 (2 per thread), store transposed
        // B tile: 16 rows x 128 cols, as 512 float4 (2 per thread)
#pragma unroll
        for (int i = 0; i < 2; i++) {
            int idx4 = tid + i * 256;
            int ra = idx4 >> 2, c4 = idx4 & 3;
            float4 a = *(const float4*)(Aptr + (size_t)ra * K + k0 + c4 * 4);
            As[c4 * 4 + 0][ra] = a.x;
            As[c4 * 4 + 1][ra] = a.y;
            As[c4 * 4 + 2][ra] = a.z;
            As[c4 * 4 + 3][ra] = a.w;
            int rb = idx4 >> 5, cb4 = idx4 & 31;
            float4 bv = *(const float4*)(Bptr + (size_t)(k0 + rb) * N + cb4 * 4);
            *(float4*)&Bs[rb][cb4 * 4] = bv;
        }
        __syncthreads();

#pragma unroll
        for (int kk = 0; kk < 16; kk++) {
            float a[8], b[8];
            *(float4*)&a[0] = *(const float4*)&As[kk][ty * 8];
            *(float4*)&a[4] = *(const float4*)&As[kk][ty * 8 + 4];
            *(float4*)&b[0] = *(const float4*)&Bs[kk][tx * 8];
            *(float4*)&b[4] = *(const float4*)&Bs[kk][tx * 8 + 4];
#pragma unroll
            for (int i = 0; i < 8; i++)
#pragma unroll
                for (int j = 0; j < 8; j++)
                    acc[i][j] += a[i] * b[j];
        }
        __syncthreads();
    }

#pragma unroll
    for (int i = 0; i < 8; i++) {
        float* crow = C + (size_t)(row0 + ty * 8 + i) * N + col0 + tx * 8;
        *(float4*)(crow)     = make_float4(acc[i][0], acc[i][1], acc[i][2], acc[i][3]);
        *(float4*)(crow + 4) = make_float4(acc[i][4], acc[i][5], acc[i][6], acc[i][7]);
    }
}

// ---------------------------------------------------------------------------
// Per-(b,h,g,d) means of q/k/v over the 256 positions of the group.
// Layout of g_qm/km/vm: [b][h][g][d] -> idx = ((b*16+h)*8+g)*64+d
// ---------------------------------------------------------------------------
__global__ void mean_kernel()
{
    int idx = blockIdx.x * blockDim.x + threadIdx.x;
    if (idx >= NMEAN) return;
    int d = idx & 63;
    int g = (idx >> 6) & 7;
    int h = (idx >> 9) & 15;
    int b = idx >> 13;
    const float* base = g_qkv + ((size_t)(b * 2048 + g * GT)) * QKVN + h * 64 + d;
    float sq = 0.f, sk = 0.f, sv = 0.f;
    for (int p = 0; p < GT; p++) {
        size_t o = (size_t)p * QKVN;
        sq += base[o];
        sk += base[o + 1024];
        sv += base[o + 2048];
    }
    const float inv = 1.f / 256.f;
    g_qm[idx] = sq * inv;
    g_km[idx] = sk * inv;
    g_vm[idx] = sv * inv;
}

// ---------------------------------------------------------------------------
// Group attention: one block per (b,h,g). L=257 (256 tokens + mean token),
// d=64, causal, scale 1/8. K/V/Q resident in smem (padded rows). Each warp
// processes query rows round-robin; scores staged per-warp in smem.
// Rows p<256 written straight into g_xo[b][t][h*64+d]; row 256 -> g_xm.
// ---------------------------------------------------------------------------
__global__ void attn_group_kernel()
{
    extern __shared__ float sm[];
    float* Qs = sm;
    float* Ks = sm + LSEQ * LSTR;
    float* Vs = sm + 2 * LSEQ * LSTR;
    float* Sc = sm + 3 * LSEQ * LSTR;   // 8 warps x 260

    const int bhg  = blockIdx.x;
    const int g    = bhg & 7;
    const int h    = (bhg >> 3) & 15;
    const int b    = bhg >> 7;
    const int tid  = threadIdx.x;
    const int lane = tid & 31;
    const int w    = tid >> 5;

    const float* qbase = g_qkv + ((size_t)(b * 2048 + g * GT)) * QKVN + h * 64;

    for (int idx = tid; idx < GT * 64; idx += 256) {
        int p = idx >> 6, d = idx & 63;
        size_t go = (size_t)p * QKVN + d;
        Qs[p * LSTR + d] = qbase[go];
        Ks[p * LSTR + d] = qbase[go + 1024];
        Vs[p * LSTR + d] = qbase[go + 2048];
    }
    if (tid < 64) {
        int moff = bhg * 64 + tid;   // ((b*16+h)*8+g)*64 + d == bhg*64+d
        Qs[256 * LSTR + tid] = g_qm[moff];
        Ks[256 * LSTR + tid] = g_km[moff];
        Vs[256 * LSTR + tid] = g_vm[moff];
    }
    __syncthreads();

    float* scrow = Sc + w * 260;

    for (int i = w; i < LSEQ; i += 8) {
        const int nj = i + 1;
        const float* qrow = Qs + i * LSTR;

        // ---- phase A: scores s[j] = (Q_i . K_j) / 8, lane owns j = lane+32t
        float s[9];
#pragma unroll
        for (int t = 0; t < 9; t++) s[t] = 0.f;

#pragma unroll
        for (int d0 = 0; d0 < 64; d0 += 16) {
            float q[16];
#pragma unroll
            for (int dd = 0; dd < 16; dd++) q[dd] = qrow[d0 + dd];
#pragma unroll
            for (int t = 0; t < 9; t++) {
                int j = lane + 32 * t;
                if (j < nj) {
                    const float* krow = Ks + j * LSTR + d0;
#pragma unroll
                    for (int dd = 0; dd < 16; dd++) s[t] += q[dd] * krow[dd];
                }
            }
        }

        float m = -3.0e38f;
#pragma unroll
        for (int t = 0; t < 9; t++) {
            int j = lane + 32 * t;
            if (j < nj) { s[t] *= 0.125f; m = fmaxf(m, s[t]); }
        }
#pragma unroll
        for (int off = 16; off; off >>= 1)
            m = fmaxf(m, __shfl_xor_sync(0xffffffffu, m, off));

        float sum = 0.f;
#pragma unroll
        for (int t = 0; t < 9; t++) {
            int j = lane + 32 * t;
            if (j < nj) {
                float p = __expf(s[t] - m);
                sum += p;
                scrow[j] = p;
            }
        }
#pragma unroll
        for (int off = 16; off; off >>= 1)
            sum += __shfl_xor_sync(0xffffffffu, sum, off);
        const float inv = 1.f / sum;
        __syncwarp();

        // ---- phase B: O_i[d] = sum_j p_j V[j][d]; lane owns d=lane, lane+32
        float o0 = 0.f, o1 = 0.f;
        for (int j = 0; j < nj; j++) {
            float p = scrow[j];
            const float* vrow = Vs + j * LSTR;
            o0 += p * vrow[lane];
            o1 += p * vrow[lane + 32];
        }
        o0 *= inv; o1 *= inv;

        if (i < 256) {
            float* orow = g_xo + ((size_t)(b * 2048 + g * GT + i)) * CDIM + h * 64;
            orow[lane]      = o0;
            orow[lane + 32] = o1;
        } else {
            float* orow = g_xm + bhg * 64;
            orow[lane]      = o0;
            orow[lane + 32] = o1;
        }
        __syncwarp();   // protect scrow before next row's phase A
    }
}

// ---------------------------------------------------------------------------
// Second attention over 7 groups (mean tokens), per (b,h). Also emits
// yq/yk copies. One block (64 threads) per (b,h).
// yq/yk/yv layout: [(b*16+h)][i in 0..6][d], i.e. (bh*7+i)*64+d
// ---------------------------------------------------------------------------
__global__ void attn_cross_kernel(float* __restrict__ yq,
                                  float* __restrict__ yk,
                                  float* __restrict__ yv)
{
    __shared__ float Q[7][64], K[7][64], V[7][64], S[7][8];
    const int bh  = blockIdx.x;   // b*16+h
    const int tid = threadIdx.x;  // 0..63  (= d)

    const float* qb = g_qm + bh * 8 * 64;
    const float* kb = g_km + bh * 8 * 64;
    const float* vb = g_xm + bh * 8 * 64;
    for (int i = 0; i < 7; i++) {
        Q[i][tid] = qb[i * 64 + tid];
        K[i][tid] = kb[i * 64 + tid];
        V[i][tid] = vb[i * 64 + tid];
    }
    __syncthreads();

    if (tid < 49) {
        int i = tid / 7, j = tid % 7;
        float s = 0.f;
#pragma unroll
        for (int d = 0; d < 64; d++) s += Q[i][d] * K[j][d];
        S[i][j] = s * 0.125f;
    }
    __syncthreads();

    for (int i = 0; i < 7; i++) {
        float m = -3.0e38f;
        for (int j = 0; j <= i; j++) m = fmaxf(m, S[i][j]);
        float p[7], sum = 0.f;
        for (int j = 0; j <= i; j++) { p[j] = __expf(S[i][j] - m); sum += p[j]; }
        float o = 0.f;
        for (int j = 0; j <= i; j++) o += p[j] * V[j][tid];
        yv[(bh * 7 + i) * 64 + tid] = o / sum;
        yq[(bh * 7 + i) * 64 + tid] = Q[i][tid];
        yk[(bh * 7 + i) * 64 + tid] = K[i][tid];
    }
}

// ---------------------------------------------------------------------------
// kernel_launch
// ---------------------------------------------------------------------------
extern "C" void kernel_launch(void* const* d_in, const int* in_sizes, int n_in,
                              void* d_out, int out_size)
{
    const float* x      = (const float*)d_in[0];   // [8,2048,1024]
    const float* W_attn = (const float*)d_in[1];   // [1024,3072]
    const float* W_proj = (const float*)d_in[2];   // [1024,1024]

    float* out = (float*)d_out;                    // 16777216
    float* yq  = out + (size_t)MTOT * CDIM;        // 57344
    float* yk  = yq + 8 * 16 * 7 * 64;
    float* yv  = yk + 8 * 16 * 7 * 64;

    // device-symbol addresses
    float *qkv_p, *xo_p;
    cudaGetSymbolAddress((void**)&qkv_p, g_qkv);
    cudaGetSymbolAddress((void**)&xo_p,  g_xo);

    // opt-in large smem for the group-attention kernel
    const int ATTN_SMEM = (3 * LSEQ * LSTR + 8 * 260) * (int)sizeof(float); // 208,780 B
    cudaFuncSetAttribute(attn_group_kernel,
                         cudaFuncAttributeMaxDynamicSharedMemorySize, ATTN_SMEM);

    // 1) qkv = x @ W_attn
    sgemm128<<<dim3(QKVN / 128, MTOT / 128), 256>>>(x, W_attn, qkv_p,
                                                    MTOT, QKVN, CDIM);
    // 2) per-(b,h,g) means
    mean_kernel<<<NMEAN / 256, 256>>>();
    // 3) group attention -> g_xo (regular rows), g_xm (mean rows)
    attn_group_kernel<<<NBHG, 256, ATTN_SMEM>>>();
    // 4) cross-group attention -> yq/yk/yv
    attn_cross_kernel<<<128, 64>>>(yq, yk, yv);
    // 5) out = xo @ W_proj
    sgemm128<<<dim3(CDIM / 128, MTOT / 128), 256>>>(xo_p, W_proj, out,
                                                    MTOT, CDIM, CDIM);
}

// round 10
// speedup vs baseline: 3.2863x; 3.2863x over previous
#include <cuda_runtime.h>
#include <cuda_bf16.h>
#include <cstdint>

// ---------------------------------------------------------------------------
// Problem constants
//   B=8, T=2048, C=1024, NHEADS=16, HSIZE=64, N_GROUPS=8, group_t=256
//   qkv = x @ W_attn            [16384 x 3072], K=1024   (TF32 tensor cores)
//   per (b,h,g): causal attn over 257 tokens (256 + mean token), d=64 (fp32)
//   second attn over 7 groups (mean tokens), d=64 (fp32)
//   out = xo @ W_proj           [16384 x 1024], K=1024   (TF32 tensor cores)
// Outputs packed: out (16777216) | yq (57344) | yk (57344) | yv (57344)
// ---------------------------------------------------------------------------

#define MTOT   16384          // B*T
#define CDIM   1024
#define QKVN   3072
#define GT     256
#define LSEQ   257
#define LSTR   65             // padded smem row stride (conflict-free)
#define NBHG   1024           // 8*16*8
#define NMEAN  65536          // 8*16*8*64

__device__ float g_qkv[(size_t)MTOT * QKVN];   // 192 MB
__device__ float g_xo [(size_t)MTOT * CDIM];   //  64 MB
__device__ float g_qm [NMEAN];
__device__ float g_km [NMEAN];
__device__ float g_vm [NMEAN];
__device__ float g_xm [NMEAN];                 // attn output at mean-token rows

// ---------------------------------------------------------------------------
// TF32 tensor-core GEMM: C[M,N] = A[M,K] @ B[K,N], fp32 in/out, tf32 MMA,
// fp32 accumulate. Block tile 128x128, BK=32, 256 threads = 8 warps (4x2),
// warp tile 32x64 (2 m16-tiles x 8 n8-tiles), cp.async double buffering.
// Requires M%128==0, N%128==0, K%32==0.
//
// smem strides: As row stride 36 floats  -> A-fragment banks (4r+c) distinct
//               Bs row stride 136 floats -> B-fragment banks (8k+n) distinct
// ---------------------------------------------------------------------------
#define AS_STAGE 4608   // 128*36
#define BS_STAGE 4352   // 32*136
#define GEMM_SMEM ((2*(AS_STAGE + BS_STAGE)) * (int)sizeof(float))  // 71680 B

__device__ __forceinline__ uint32_t f2tf32(float f)
{
    uint32_t r;
    asm("cvt.rna.tf32.f32 %0, %1;" : "=r"(r) : "f"(f));
    return r;
}

__global__ __launch_bounds__(256)
void gemm_tf32(const float* __restrict__ A, const float* __restrict__ B,
               float* __restrict__ C, int M, int N, int K)
{
    extern __shared__ float smem[];
    float* As = smem;                   // [2][128][36]
    float* Bs = smem + 2 * AS_STAGE;    // [2][32][136]

    const int tid  = threadIdx.x;
    const int lane = tid & 31;
    const int w    = tid >> 5;
    const int wm0  = (w >> 1) * 32;     // warp m-offset (4 warp-rows)
    const int wn0  = (w & 1) * 64;      // warp n-offset (2 warp-cols)
    const int row0 = blockIdx.y * 128;
    const int col0 = blockIdx.x * 128;

    const int r  = lane >> 2;           // groupID (0..7)
    const int cq = lane & 3;            // thread-in-group (0..3)

    float acc[2][8][4];
#pragma unroll
    for (int mt = 0; mt < 2; mt++)
#pragma unroll
        for (int nt = 0; nt < 8; nt++)
#pragma unroll
            for (int q = 0; q < 4; q++) acc[mt][nt][q] = 0.f;

    const int nk = K >> 5;   // K / 32

    // ---- async prefetch of tile t into stage s
    auto prefetch = [&](int t, int s) {
        const float* Ab = A + (size_t)row0 * K + t * 32;
        const float* Bb = B + (size_t)(t * 32) * N + col0;
        float* as = As + s * AS_STAGE;
        float* bs = Bs + s * BS_STAGE;
#pragma unroll
        for (int i = 0; i < 4; i++) {
            int idx4 = tid + i * 256;            // 0..1023
            int m  = idx4 >> 3, k4 = idx4 & 7;   // A: 128 rows x 8 float4
            uint32_t da = (uint32_t)__cvta_generic_to_shared(as + m * 36 + k4 * 4);
            const float* sa = Ab + (size_t)m * K + k4 * 4;
            asm volatile("cp.async.cg.shared.global [%0], [%1], 16;" :: "r"(da), "l"(sa));
            int kb = idx4 >> 5, n4 = idx4 & 31;  // B: 32 rows x 32 float4
            uint32_t db = (uint32_t)__cvta_generic_to_shared(bs + kb * 136 + n4 * 4);
            const float* sb = Bb + (size_t)kb * N + n4 * 4;
            asm volatile("cp.async.cg.shared.global [%0], [%1], 16;" :: "r"(db), "l"(sb));
        }
        asm volatile("cp.async.commit_group;");
    };

    prefetch(0, 0);

    for (int t = 0; t < nk; t++) {
        asm volatile("cp.async.wait_group 0;");
        __syncthreads();
        if (t + 1 < nk) prefetch(t + 1, (t + 1) & 1);

        const float* as = As + (t & 1) * AS_STAGE;
        const float* bs = Bs + (t & 1) * BS_STAGE;

#pragma unroll
        for (int kk = 0; kk < 4; kk++) {
            const int k = kk * 8;
            uint32_t af[2][4], bf[8][2];
#pragma unroll
            for (int mt = 0; mt < 2; mt++) {
                const float* ap = as + (wm0 + mt * 16 + r) * 36 + k + cq;
                af[mt][0] = f2tf32(ap[0]);
                af[mt][1] = f2tf32(ap[8 * 36]);
                af[mt][2] = f2tf32(ap[4]);
                af[mt][3] = f2tf32(ap[8 * 36 + 4]);
            }
#pragma unroll
            for (int nt = 0; nt < 8; nt++) {
                const float* bp = bs + (k + cq) * 136 + wn0 + nt * 8 + r;
                bf[nt][0] = f2tf32(bp[0]);
                bf[nt][1] = f2tf32(bp[4 * 136]);
            }
#pragma unroll
            for (int mt = 0; mt < 2; mt++)
#pragma unroll
                for (int nt = 0; nt < 8; nt++)
                    asm volatile(
                        "mma.sync.aligned.m16n8k8.row.col.f32.tf32.tf32.f32 "
                        "{%0,%1,%2,%3}, {%4,%5,%6,%7}, {%8,%9}, {%0,%1,%2,%3};"
                        : "+f"(acc[mt][nt][0]), "+f"(acc[mt][nt][1]),
                          "+f"(acc[mt][nt][2]), "+f"(acc[mt][nt][3])
                        : "r"(af[mt][0]), "r"(af[mt][1]), "r"(af[mt][2]), "r"(af[mt][3]),
                          "r"(bf[nt][0]), "r"(bf[nt][1]));
        }
        __syncthreads();
    }

    // ---- epilogue: fragment layout c0:(r, 2cq) c1:(r, 2cq+1) c2/c3: row+8
#pragma unroll
    for (int mt = 0; mt < 2; mt++) {
        const int rb = row0 + wm0 + mt * 16 + r;
#pragma unroll
        for (int nt = 0; nt < 8; nt++) {
            const int cb = col0 + wn0 + nt * 8 + cq * 2;
            *(float2*)(C + (size_t)rb * N + cb) =
                make_float2(acc[mt][nt][0], acc[mt][nt][1]);
            *(float2*)(C + (size_t)(rb + 8) * N + cb) =
                make_float2(acc[mt][nt][2], acc[mt][nt][3]);
        }
    }
}

// ---------------------------------------------------------------------------
// Per-(b,h,g,d) means of q/k/v over the 256 positions of the group.
// Layout of g_qm/km/vm: [b][h][g][d] -> idx = ((b*16+h)*8+g)*64+d
// ---------------------------------------------------------------------------
__global__ void mean_kernel()
{
    int idx = blockIdx.x * blockDim.x + threadIdx.x;
    if (idx >= NMEAN) return;
    int d = idx & 63;
    int g = (idx >> 6) & 7;
    int h = (idx >> 9) & 15;
    int b = idx >> 13;
    const float* base = g_qkv + ((size_t)(b * 2048 + g * GT)) * QKVN + h * 64 + d;
    float sq = 0.f, sk = 0.f, sv = 0.f;
    for (int p = 0; p < GT; p++) {
        size_t o = (size_t)p * QKVN;
        sq += base[o];
        sk += base[o + 1024];
        sv += base[o + 2048];
    }
    const float inv = 1.f / 256.f;
    g_qm[idx] = sq * inv;
    g_km[idx] = sk * inv;
    g_vm[idx] = sv * inv;
}

// ---------------------------------------------------------------------------
// Group attention: one block per (b,h,g). L=257 (256 tokens + mean token),
// d=64, causal, scale 1/8. K/V/Q resident in smem (padded rows). Each warp
// processes query rows round-robin; scores staged per-warp in smem.
// Rows p<256 written straight into g_xo[b][t][h*64+d]; row 256 -> g_xm.
// ---------------------------------------------------------------------------
__global__ void attn_group_kernel()
{
    extern __shared__ float sm[];
    float* Qs = sm;
    float* Ks = sm + LSEQ * LSTR;
    float* Vs = sm + 2 * LSEQ * LSTR;
    float* Sc = sm + 3 * LSEQ * LSTR;   // 8 warps x 260

    const int bhg  = blockIdx.x;
    const int g    = bhg & 7;
    const int h    = (bhg >> 3) & 15;
    const int b    = bhg >> 7;
    const int tid  = threadIdx.x;
    const int lane = tid & 31;
    const int w    = tid >> 5;

    const float* qbase = g_qkv + ((size_t)(b * 2048 + g * GT)) * QKVN + h * 64;

    for (int idx = tid; idx < GT * 64; idx += 256) {
        int p = idx >> 6, d = idx & 63;
        size_t go = (size_t)p * QKVN + d;
        Qs[p * LSTR + d] = qbase[go];
        Ks[p * LSTR + d] = qbase[go + 1024];
        Vs[p * LSTR + d] = qbase[go + 2048];
    }
    if (tid < 64) {
        int moff = bhg * 64 + tid;   // ((b*16+h)*8+g)*64 + d == bhg*64+d
        Qs[256 * LSTR + tid] = g_qm[moff];
        Ks[256 * LSTR + tid] = g_km[moff];
        Vs[256 * LSTR + tid] = g_vm[moff];
    }
    __syncthreads();

    float* scrow = Sc + w * 260;

    for (int i = w; i < LSEQ; i += 8) {
        const int nj = i + 1;
        const float* qrow = Qs + i * LSTR;

        // ---- phase A: scores s[j] = (Q_i . K_j) / 8, lane owns j = lane+32t
        float s[9];
#pragma unroll
        for (int t = 0; t < 9; t++) s[t] = 0.f;

#pragma unroll
        for (int d0 = 0; d0 < 64; d0 += 16) {
            float q[16];
#pragma unroll
            for (int dd = 0; dd < 16; dd++) q[dd] = qrow[d0 + dd];
#pragma unroll
            for (int t = 0; t < 9; t++) {
                int j = lane + 32 * t;
                if (j < nj) {
                    const float* krow = Ks + j * LSTR + d0;
#pragma unroll
                    for (int dd = 0; dd < 16; dd++) s[t] += q[dd] * krow[dd];
                }
            }
        }

        float m = -3.0e38f;
#pragma unroll
        for (int t = 0; t < 9; t++) {
            int j = lane + 32 * t;
            if (j < nj) { s[t] *= 0.125f; m = fmaxf(m, s[t]); }
        }
#pragma unroll
        for (int off = 16; off; off >>= 1)
            m = fmaxf(m, __shfl_xor_sync(0xffffffffu, m, off));

        float sum = 0.f;
#pragma unroll
        for (int t = 0; t < 9; t++) {
            int j = lane + 32 * t;
            if (j < nj) {
                float p = __expf(s[t] - m);
                sum += p;
                scrow[j] = p;
            }
        }
#pragma unroll
        for (int off = 16; off; off >>= 1)
            sum += __shfl_xor_sync(0xffffffffu, sum, off);
        const float inv = 1.f / sum;
        __syncwarp();

        // ---- phase B: O_i[d] = sum_j p_j V[j][d]; lane owns d=lane, lane+32
        float o0 = 0.f, o1 = 0.f;
        for (int j = 0; j < nj; j++) {
            float p = scrow[j];
            const float* vrow = Vs + j * LSTR;
            o0 += p * vrow[lane];
            o1 += p * vrow[lane + 32];
        }
        o0 *= inv; o1 *= inv;

        if (i < 256) {
            float* orow = g_xo + ((size_t)(b * 2048 + g * GT + i)) * CDIM + h * 64;
            orow[lane]      = o0;
            orow[lane + 32] = o1;
        } else {
            float* orow = g_xm + bhg * 64;
            orow[lane]      = o0;
            orow[lane + 32] = o1;
        }
        __syncwarp();   // protect scrow before next row's phase A
    }
}

// ---------------------------------------------------------------------------
// Second attention over 7 groups (mean tokens), per (b,h). Also emits
// yq/yk copies. One block (64 threads) per (b,h).
// yq/yk/yv layout: [(b*16+h)][i in 0..6][d], i.e. (bh*7+i)*64+d
// ---------------------------------------------------------------------------
__global__ void attn_cross_kernel(float* __restrict__ yq,
                                  float* __restrict__ yk,
                                  float* __restrict__ yv)
{
    __shared__ float Q[7][64], K[7][64], V[7][64], S[7][8];
    const int bh  = blockIdx.x;   // b*16+h
    const int tid = threadIdx.x;  // 0..63  (= d)

    const float* qb = g_qm + bh * 8 * 64;
    const float* kb = g_km + bh * 8 * 64;
    const float* vb = g_xm + bh * 8 * 64;
    for (int i = 0; i < 7; i++) {
        Q[i][tid] = qb[i * 64 + tid];
        K[i][tid] = kb[i * 64 + tid];
        V[i][tid] = vb[i * 64 + tid];
    }
    __syncthreads();

    if (tid < 49) {
        int i = tid / 7, j = tid % 7;
        float s = 0.f;
#pragma unroll
        for (int d = 0; d < 64; d++) s += Q[i][d] * K[j][d];
        S[i][j] = s * 0.125f;
    }
    __syncthreads();

    for (int i = 0; i < 7; i++) {
        float m = -3.0e38f;
        for (int j = 0; j <= i; j++) m = fmaxf(m, S[i][j]);
        float p[7], sum = 0.f;
        for (int j = 0; j <= i; j++) { p[j] = __expf(S[i][j] - m); sum += p[j]; }
        float o = 0.f;
        for (int j = 0; j <= i; j++) o += p[j] * V[j][tid];
        yv[(bh * 7 + i) * 64 + tid] = o / sum;
        yq[(bh * 7 + i) * 64 + tid] = Q[i][tid];
        yk[(bh * 7 + i) * 64 + tid] = K[i][tid];
    }
}

// ---------------------------------------------------------------------------
// kernel_launch
// ---------------------------------------------------------------------------
extern "C" void kernel_launch(void* const* d_in, const int* in_sizes, int n_in,
                              void* d_out, int out_size)
{
    const float* x      = (const float*)d_in[0];   // [8,2048,1024]
    const float* W_attn = (const float*)d_in[1];   // [1024,3072]
    const float* W_proj = (const float*)d_in[2];   // [1024,1024]

    float* out = (float*)d_out;                    // 16777216
    float* yq  = out + (size_t)MTOT * CDIM;        // 57344
    float* yk  = yq + 8 * 16 * 7 * 64;
    float* yv  = yk + 8 * 16 * 7 * 64;

    // device-symbol addresses
    float *qkv_p, *xo_p;
    cudaGetSymbolAddress((void**)&qkv_p, g_qkv);
    cudaGetSymbolAddress((void**)&xo_p,  g_xo);

    // opt-in large smem
    const int ATTN_SMEM = (3 * LSEQ * LSTR + 8 * 260) * (int)sizeof(float); // 208,780 B
    cudaFuncSetAttribute(attn_group_kernel,
                         cudaFuncAttributeMaxDynamicSharedMemorySize, ATTN_SMEM);
    cudaFuncSetAttribute(gemm_tf32,
                         cudaFuncAttributeMaxDynamicSharedMemorySize, GEMM_SMEM);

    // 1) qkv = x @ W_attn   (TF32 tensor cores)
    gemm_tf32<<<dim3(QKVN / 128, MTOT / 128), 256, GEMM_SMEM>>>(
        x, W_attn, qkv_p, MTOT, QKVN, CDIM);
    // 2) per-(b,h,g) means
    mean_kernel<<<NMEAN / 256, 256>>>();
    // 3) group attention -> g_xo (regular rows), g_xm (mean rows)
    attn_group_kernel<<<NBHG, 256, ATTN_SMEM>>>();
    // 4) cross-group attention -> yq/yk/yv
    attn_cross_kernel<<<128, 64>>>(yq, yk, yv);
    // 5) out = xo @ W_proj  (TF32 tensor cores)
    gemm_tf32<<<dim3(CDIM / 128, MTOT / 128), 256, GEMM_SMEM>>>(
        xo_p, W_proj, out, MTOT, CDIM, CDIM);
}

// round 11
// speedup vs baseline: 5.4031x; 1.6442x over previous
#include <cuda_runtime.h>
#include <cuda_bf16.h>
#include <cstdint>

// ---------------------------------------------------------------------------
// Problem constants
//   B=8, T=2048, C=1024, NHEADS=16, HSIZE=64, N_GROUPS=8, group_t=256
//   qkv = x @ W_attn            [16384 x 3072], K=1024   (TF32 tensor cores)
//   per (b,h,g): causal attn over 257 tokens (256 + mean token), d=64
//                -> rows <256 never see the mean token (causal) => 256x256
//                   causal attention on tensor cores + 1 scalar mean row
//   second attn over 7 groups (mean tokens), d=64 (fp32)
//   out = xo @ W_proj           [16384 x 1024], K=1024   (TF32 tensor cores)
// Outputs packed: out (16777216) | yq (57344) | yk (57344) | yv (57344)
// ---------------------------------------------------------------------------

#define MTOT   16384          // B*T
#define CDIM   1024
#define QKVN   3072
#define GT     256
#define NBHG   1024           // 8*16*8
#define NMEAN  65536          // 8*16*8*64

__device__ float g_qkv[(size_t)MTOT * QKVN];   // 192 MB
__device__ float g_xo [(size_t)MTOT * CDIM];   //  64 MB
__device__ float g_qm [NMEAN];
__device__ float g_km [NMEAN];
__device__ float g_vm [NMEAN];
__device__ float g_xm [NMEAN];                 // attn output at mean-token rows

__device__ __forceinline__ uint32_t f2tf32(float f)
{
    uint32_t r;
    asm("cvt.rna.tf32.f32 %0, %1;" : "=r"(r) : "f"(f));
    return r;
}

// 2^z for z <= 0, FFMA-only (no MUFU). |rel err| < ~2e-7.
__device__ __forceinline__ float ex2p(float z)
{
    z = fmaxf(z, -100.f);
    float t = z + 12582912.f;                      // round-to-nearest int
    int   n = __float_as_int(t) - 0x4B400000;
    float f = z - (t - 12582912.f);                // f in [-0.5, 0.5]
    float p = 0.0013333558f;
    p = fmaf(p, f, 0.0096181291f);
    p = fmaf(p, f, 0.0555041087f);
    p = fmaf(p, f, 0.2402265069f);
    p = fmaf(p, f, 0.6931471806f);
    p = fmaf(p, f, 1.0f);
    return __int_as_float(__float_as_int(p) + (n << 23));
}

__device__ __forceinline__ void mma_tf32(float* c, const uint32_t* a,
                                         uint32_t b0, uint32_t b1)
{
    asm volatile(
        "mma.sync.aligned.m16n8k8.row.col.f32.tf32.tf32.f32 "
        "{%0,%1,%2,%3}, {%4,%5,%6,%7}, {%8,%9}, {%0,%1,%2,%3};"
        : "+f"(c[0]), "+f"(c[1]), "+f"(c[2]), "+f"(c[3])
        : "r"(a[0]), "r"(a[1]), "r"(a[2]), "r"(a[3]), "r"(b0), "r"(b1));
}

// ---------------------------------------------------------------------------
// TF32 tensor-core GEMM (unchanged from R10): 128x128 block, BK=32, 8 warps.
// ---------------------------------------------------------------------------
#define AS_STAGE 4608   // 128*36
#define BS_STAGE 4352   // 32*136
#define GEMM_SMEM ((2*(AS_STAGE + BS_STAGE)) * (int)sizeof(float))  // 71680 B

__global__ __launch_bounds__(256)
void gemm_tf32(const float* __restrict__ A, const float* __restrict__ B,
               float* __restrict__ C, int M, int N, int K)
{
    extern __shared__ float smem[];
    float* As = smem;
    float* Bs = smem + 2 * AS_STAGE;

    const int tid  = threadIdx.x;
    const int lane = tid & 31;
    const int w    = tid >> 5;
    const int wm0  = (w >> 1) * 32;
    const int wn0  = (w & 1) * 64;
    const int row0 = blockIdx.y * 128;
    const int col0 = blockIdx.x * 128;
    const int r  = lane >> 2;
    const int cq = lane & 3;

    float acc[2][8][4];
#pragma unroll
    for (int mt = 0; mt < 2; mt++)
#pragma unroll
        for (int nt = 0; nt < 8; nt++)
#pragma unroll
            for (int q = 0; q < 4; q++) acc[mt][nt][q] = 0.f;

    const int nk = K >> 5;

    auto prefetch = [&](int t, int s) {
        const float* Ab = A + (size_t)row0 * K + t * 32;
        const float* Bb = B + (size_t)(t * 32) * N + col0;
        float* as = As + s * AS_STAGE;
        float* bs = Bs + s * BS_STAGE;
#pragma unroll
        for (int i = 0; i < 4; i++) {
            int idx4 = tid + i * 256;
            int m  = idx4 >> 3, k4 = idx4 & 7;
            uint32_t da = (uint32_t)__cvta_generic_to_shared(as + m * 36 + k4 * 4);
            const float* sa = Ab + (size_t)m * K + k4 * 4;
            asm volatile("cp.async.cg.shared.global [%0], [%1], 16;" :: "r"(da), "l"(sa));
            int kb = idx4 >> 5, n4 = idx4 & 31;
            uint32_t db = (uint32_t)__cvta_generic_to_shared(bs + kb * 136 + n4 * 4);
            const float* sb = Bb + (size_t)kb * N + n4 * 4;
            asm volatile("cp.async.cg.shared.global [%0], [%1], 16;" :: "r"(db), "l"(sb));
        }
        asm volatile("cp.async.commit_group;");
    };

    prefetch(0, 0);

    for (int t = 0; t < nk; t++) {
        asm volatile("cp.async.wait_group 0;");
        __syncthreads();
        if (t + 1 < nk) prefetch(t + 1, (t + 1) & 1);

        const float* as = As + (t & 1) * AS_STAGE;
        const float* bs = Bs + (t & 1) * BS_STAGE;

#pragma unroll
        for (int kk = 0; kk < 4; kk++) {
            const int k = kk * 8;
            uint32_t af[2][4], bf[8][2];
#pragma unroll
            for (int mt = 0; mt < 2; mt++) {
                const float* ap = as + (wm0 + mt * 16 + r) * 36 + k + cq;
                af[mt][0] = f2tf32(ap[0]);
                af[mt][1] = f2tf32(ap[8 * 36]);
                af[mt][2] = f2tf32(ap[4]);
                af[mt][3] = f2tf32(ap[8 * 36 + 4]);
            }
#pragma unroll
            for (int nt = 0; nt < 8; nt++) {
                const float* bp = bs + (k + cq) * 136 + wn0 + nt * 8 + r;
                bf[nt][0] = f2tf32(bp[0]);
                bf[nt][1] = f2tf32(bp[4 * 136]);
            }
#pragma unroll
            for (int mt = 0; mt < 2; mt++)
#pragma unroll
                for (int nt = 0; nt < 8; nt++)
                    mma_tf32(acc[mt][nt], af[mt], bf[nt][0], bf[nt][1]);
        }
        __syncthreads();
    }

#pragma unroll
    for (int mt = 0; mt < 2; mt++) {
        const int rb = row0 + wm0 + mt * 16 + r;
#pragma unroll
        for (int nt = 0; nt < 8; nt++) {
            const int cb = col0 + wn0 + nt * 8 + cq * 2;
            *(float2*)(C + (size_t)rb * N + cb) =
                make_float2(acc[mt][nt][0], acc[mt][nt][1]);
            *(float2*)(C + (size_t)(rb + 8) * N + cb) =
                make_float2(acc[mt][nt][2], acc[mt][nt][3]);
        }
    }
}

// ---------------------------------------------------------------------------
// Per-(b,h,g,d) means of q/k/v over the 256 positions of the group.
// ---------------------------------------------------------------------------
__global__ void mean_kernel()
{
    int idx = blockIdx.x * blockDim.x + threadIdx.x;
    if (idx >= NMEAN) return;
    int d = idx & 63;
    int g = (idx >> 6) & 7;
    int h = (idx >> 9) & 15;
    int b = idx >> 13;
    const float* base = g_qkv + ((size_t)(b * 2048 + g * GT)) * QKVN + h * 64 + d;
    float sq = 0.f, sk = 0.f, sv = 0.f;
    for (int p = 0; p < GT; p++) {
        size_t o = (size_t)p * QKVN;
        sq += base[o];
        sk += base[o + 1024];
        sv += base[o + 2048];
    }
    const float inv = 1.f / 256.f;
    g_qm[idx] = sq * inv;
    g_km[idx] = sk * inv;
    g_vm[idx] = sv * inv;
}

// ---------------------------------------------------------------------------
// Group attention (tensor-core): one block per (b,h,g), 288 threads.
//   warps 0..7: 256x256 causal attention via m16n8k8 tf32 MMA, flash-style
//     online softmax in log2 units (scale 0.125*log2e folded into Q frags).
//     Warp w owns row-tiles {w, 15-w} -> 9 j-chunks each (balanced).
//   warp 8: the mean-token row (attends all 257 keys incl. itself), scalar.
// Smem: Ks (tf32-truncated) 257x68 | Vs (fp32) 257x68 | P scratch 8x16x36 | Qm
// ---------------------------------------------------------------------------
#define KSTR 68
#define ATTN_SMEM_F (2 * 257 * KSTR + 8 * 16 * 36 + 64)   // 39624 floats
#define L2E 1.4426950408889634f

__global__ __launch_bounds__(288)
void attn_group_mma()
{
    extern __shared__ float sm[];
    float* Ks = sm;                       // 257*68 (tf32-truncated values)
    float* Vs = sm + 257 * KSTR;          // 257*68 (fp32)
    float* Ps = sm + 2 * 257 * KSTR;      // 8 * 576
    float* Qm = Ps + 8 * 576;             // 64

    const int bhg  = blockIdx.x;
    const int g    = bhg & 7;
    const int h    = (bhg >> 3) & 15;
    const int b    = bhg >> 7;
    const int tid  = threadIdx.x;
    const int lane = tid & 31;
    const int w    = tid >> 5;
    const int brow = b * 2048 + g * GT;
    const float* qkvb = g_qkv + (size_t)brow * QKVN + h * 64;

    for (int idx = tid; idx < GT * 64; idx += 288) {
        int p = idx >> 6, d = idx & 63;
        const float* src = qkvb + (size_t)p * QKVN + d;
        Ks[p * KSTR + d] = __uint_as_float(f2tf32(src[1024]));
        Vs[p * KSTR + d] = src[2048];
    }
    if (tid < 64) {
        Ks[256 * KSTR + tid] = __uint_as_float(f2tf32(g_km[bhg * 64 + tid]));
        Vs[256 * KSTR + tid] = g_vm[bhg * 64 + tid];
        Qm[tid] = g_qm[bhg * 64 + tid];
    }
    __syncthreads();

    const int r  = lane >> 2;
    const int cq = lane & 3;
    const float QS = 0.125f * L2E;        // scores in log2 units

    if (w < 8) {
        float* myP = Ps + w * 576;

        for (int half = 0; half < 2; half++) {
            const int tile = half ? (15 - w) : w;
            const int i0 = tile * 16;

            // Q fragments straight from gmem, pre-scaled by 0.125*log2e
            uint32_t qf[8][4];
            const float* qg = qkvb + (size_t)i0 * QKVN;
#pragma unroll
            for (int kc = 0; kc < 8; kc++) {
                qf[kc][0] = f2tf32(QS * qg[(size_t)r * QKVN + kc * 8 + cq]);
                qf[kc][1] = f2tf32(QS * qg[(size_t)(r + 8) * QKVN + kc * 8 + cq]);
                qf[kc][2] = f2tf32(QS * qg[(size_t)r * QKVN + kc * 8 + cq + 4]);
                qf[kc][3] = f2tf32(QS * qg[(size_t)(r + 8) * QKVN + kc * 8 + cq + 4]);
            }

            float m0 = -1e30f, m1 = -1e30f, l0 = 0.f, l1 = 0.f;
            float oacc[8][4];
#pragma unroll
            for (int nt = 0; nt < 8; nt++)
#pragma unroll
                for (int q = 0; q < 4; q++) oacc[nt][q] = 0.f;

            const int nch = (i0 + 15) / 32 + 1;
            for (int c = 0; c < nch; c++) {
                const int j0 = c * 32;

                // ---- S = Q K^T (log2 units), 4 n8-tiles
                float s[4][4];
#pragma unroll
                for (int nt = 0; nt < 4; nt++) {
                    s[nt][0] = s[nt][1] = s[nt][2] = s[nt][3] = 0.f;
                    const float* kb = Ks + (j0 + nt * 8 + r) * KSTR;
#pragma unroll
                    for (int kc = 0; kc < 8; kc++) {
                        uint32_t b0 = __float_as_uint(kb[kc * 8 + cq]);
                        uint32_t b1 = __float_as_uint(kb[kc * 8 + cq + 4]);
                        mma_tf32(s[nt], qf[kc], b0, b1);
                    }
                }

                // ---- causal mask
                if (j0 + 31 > i0) {
#pragma unroll
                    for (int nt = 0; nt < 4; nt++) {
                        int j = j0 + nt * 8 + 2 * cq;
                        if (j     > i0 + r)     s[nt][0] = -1e30f;
                        if (j + 1 > i0 + r)     s[nt][1] = -1e30f;
                        if (j     > i0 + r + 8) s[nt][2] = -1e30f;
                        if (j + 1 > i0 + r + 8) s[nt][3] = -1e30f;
                    }
                }

                // ---- online softmax (log2 domain)
                float cm0 = -1e30f, cm1 = -1e30f;
#pragma unroll
                for (int nt = 0; nt < 4; nt++) {
                    cm0 = fmaxf(cm0, fmaxf(s[nt][0], s[nt][1]));
                    cm1 = fmaxf(cm1, fmaxf(s[nt][2], s[nt][3]));
                }
                cm0 = fmaxf(cm0, __shfl_xor_sync(0xffffffffu, cm0, 1));
                cm0 = fmaxf(cm0, __shfl_xor_sync(0xffffffffu, cm0, 2));
                cm1 = fmaxf(cm1, __shfl_xor_sync(0xffffffffu, cm1, 1));
                cm1 = fmaxf(cm1, __shfl_xor_sync(0xffffffffu, cm1, 2));
                float mn0 = fmaxf(m0, cm0), mn1 = fmaxf(m1, cm1);
                float a0 = ex2p(m0 - mn0), a1 = ex2p(m1 - mn1);
                m0 = mn0; m1 = mn1;
                l0 *= a0; l1 *= a1;
#pragma unroll
                for (int nt = 0; nt < 8; nt++) {
                    oacc[nt][0] *= a0; oacc[nt][1] *= a0;
                    oacc[nt][2] *= a1; oacc[nt][3] *= a1;
                }
#pragma unroll
                for (int nt = 0; nt < 4; nt++) {
                    float p0 = ex2p(s[nt][0] - m0), p1 = ex2p(s[nt][1] - m0);
                    float p2 = ex2p(s[nt][2] - m1), p3 = ex2p(s[nt][3] - m1);
                    l0 += p0 + p1; l1 += p2 + p3;
                    int jl = nt * 8 + 2 * cq;
                    myP[r * 36 + jl]           = p0;
                    myP[r * 36 + jl + 1]       = p1;
                    myP[(r + 8) * 36 + jl]     = p2;
                    myP[(r + 8) * 36 + jl + 1] = p3;
                }
                __syncwarp();

                // ---- O += P V
#pragma unroll
                for (int kc = 0; kc < 4; kc++) {
                    uint32_t af[4];
                    af[0] = f2tf32(myP[r * 36 + kc * 8 + cq]);
                    af[1] = f2tf32(myP[(r + 8) * 36 + kc * 8 + cq]);
                    af[2] = f2tf32(myP[r * 36 + kc * 8 + cq + 4]);
                    af[3] = f2tf32(myP[(r + 8) * 36 + kc * 8 + cq + 4]);
                    const float* vb0 = Vs + (j0 + kc * 8 + cq) * KSTR;
                    const float* vb1 = Vs + (j0 + kc * 8 + cq + 4) * KSTR;
#pragma unroll
                    for (int nt = 0; nt < 8; nt++) {
                        uint32_t b0 = f2tf32(vb0[nt * 8 + r]);
                        uint32_t b1 = f2tf32(vb1[nt * 8 + r]);
                        mma_tf32(oacc[nt], af, b0, b1);
                    }
                }
                __syncwarp();
            }

            // ---- finalize
            l0 += __shfl_xor_sync(0xffffffffu, l0, 1);
            l0 += __shfl_xor_sync(0xffffffffu, l0, 2);
            l1 += __shfl_xor_sync(0xffffffffu, l1, 1);
            l1 += __shfl_xor_sync(0xffffffffu, l1, 2);
            float inv0 = 1.f / l0, inv1 = 1.f / l1;
            float* o0row = g_xo + (size_t)(brow + i0 + r) * CDIM + h * 64;
            float* o1row = g_xo + (size_t)(brow + i0 + r + 8) * CDIM + h * 64;
#pragma unroll
            for (int nt = 0; nt < 8; nt++) {
                *(float2*)(o0row + nt * 8 + 2 * cq) =
                    make_float2(oacc[nt][0] * inv0, oacc[nt][1] * inv0);
                *(float2*)(o1row + nt * 8 + 2 * cq) =
                    make_float2(oacc[nt][2] * inv1, oacc[nt][3] * inv1);
            }
        }
    } else {
        // ---- warp 8: mean-token row (i = 256 attends j = 0..256)
        float s[9];
#pragma unroll
        for (int t = 0; t < 9; t++) s[t] = 0.f;
#pragma unroll
        for (int d0 = 0; d0 < 64; d0 += 16) {
            float q[16];
#pragma unroll
            for (int dd = 0; dd < 16; dd++) q[dd] = Qm[d0 + dd];
#pragma unroll
            for (int t = 0; t < 9; t++) {
                int j = lane + 32 * t;
                if (j < 257) {
                    const float* kb = Ks + j * KSTR + d0;
#pragma unroll
                    for (int dd = 0; dd < 16; dd++) s[t] += q[dd] * kb[dd];
                }
            }
        }
        float m = -1e30f;
#pragma unroll
        for (int t = 0; t < 9; t++) {
            int j = lane + 32 * t;
            if (j < 257) { s[t] *= QS; m = fmaxf(m, s[t]); }
        }
#pragma unroll
        for (int off = 16; off; off >>= 1)
            m = fmaxf(m, __shfl_xor_sync(0xffffffffu, m, off));
        float p[9]; float sum = 0.f;
#pragma unroll
        for (int t = 0; t < 9; t++) {
            int j = lane + 32 * t;
            p[t] = (j < 257) ? ex2p(s[t] - m) : 0.f;
            sum += p[t];
        }
#pragma unroll
        for (int off = 16; off; off >>= 1)
            sum += __shfl_xor_sync(0xffffffffu, sum, off);
        const float inv = 1.f / sum;
        float o0 = 0.f, o1 = 0.f;
        for (int t = 0; t < 9; t++) {
            int jmax = (t < 8) ? 32 : 1;
            for (int jj = 0; jj < jmax; jj++) {
                int j = 32 * t + jj;
                float pj = __shfl_sync(0xffffffffu, p[t], jj);
                o0 += pj * Vs[j * KSTR + lane];
                o1 += pj * Vs[j * KSTR + lane + 32];
            }
        }
        g_xm[bhg * 64 + lane]      = o0 * inv;
        g_xm[bhg * 64 + lane + 32] = o1 * inv;
    }
}

// ---------------------------------------------------------------------------
// Second attention over 7 groups (mean tokens), per (b,h). Emits yq/yk/yv.
// ---------------------------------------------------------------------------
__global__ void attn_cross_kernel(float* __restrict__ yq,
                                  float* __restrict__ yk,
                                  float* __restrict__ yv)
{
    __shared__ float Q[7][64], K[7][64], V[7][64], S[7][8];
    const int bh  = blockIdx.x;
    const int tid = threadIdx.x;

    const float* qb = g_qm + bh * 8 * 64;
    const float* kb = g_km + bh * 8 * 64;
    const float* vb = g_xm + bh * 8 * 64;
    for (int i = 0; i < 7; i++) {
        Q[i][tid] = qb[i * 64 + tid];
        K[i][tid] = kb[i * 64 + tid];
        V[i][tid] = vb[i * 64 + tid];
    }
    __syncthreads();

    if (tid < 49) {
        int i = tid / 7, j = tid % 7;
        float s = 0.f;
#pragma unroll
        for (int d = 0; d < 64; d++) s += Q[i][d] * K[j][d];
        S[i][j] = s * 0.125f;
    }
    __syncthreads();

    for (int i = 0; i < 7; i++) {
        float m = -3.0e38f;
        for (int j = 0; j <= i; j++) m = fmaxf(m, S[i][j]);
        float p[7], sum = 0.f;
        for (int j = 0; j <= i; j++) { p[j] = __expf(S[i][j] - m); sum += p[j]; }
        float o = 0.f;
        for (int j = 0; j <= i; j++) o += p[j] * V[j][tid];
        yv[(bh * 7 + i) * 64 + tid] = o / sum;
        yq[(bh * 7 + i) * 64 + tid] = Q[i][tid];
        yk[(bh * 7 + i) * 64 + tid] = K[i][tid];
    }
}

// ---------------------------------------------------------------------------
// kernel_launch
// ---------------------------------------------------------------------------
extern "C" void kernel_launch(void* const* d_in, const int* in_sizes, int n_in,
                              void* d_out, int out_size)
{
    const float* x      = (const float*)d_in[0];
    const float* W_attn = (const float*)d_in[1];
    const float* W_proj = (const float*)d_in[2];

    float* out = (float*)d_out;
    float* yq  = out + (size_t)MTOT * CDIM;
    float* yk  = yq + 8 * 16 * 7 * 64;
    float* yv  = yk + 8 * 16 * 7 * 64;

    float *qkv_p, *xo_p;
    cudaGetSymbolAddress((void**)&qkv_p, g_qkv);
    cudaGetSymbolAddress((void**)&xo_p,  g_xo);

    const int ATTN_SMEM = ATTN_SMEM_F * (int)sizeof(float);   // 158,496 B
    cudaFuncSetAttribute(attn_group_mma,
                         cudaFuncAttributeMaxDynamicSharedMemorySize, ATTN_SMEM);
    cudaFuncSetAttribute(gemm_tf32,
                         cudaFuncAttributeMaxDynamicSharedMemorySize, GEMM_SMEM);

    // 1) qkv = x @ W_attn   (TF32 tensor cores)
    gemm_tf32<<<dim3(QKVN / 128, MTOT / 128), 256, GEMM_SMEM>>>(
        x, W_attn, qkv_p, MTOT, QKVN, CDIM);
    // 2) per-(b,h,g) means
    mean_kernel<<<NMEAN / 256, 256>>>();
    // 3) group attention (tensor cores) -> g_xo, g_xm
    attn_group_mma<<<NBHG, 288, ATTN_SMEM>>>();
    // 4) cross-group attention -> yq/yk/yv
    attn_cross_kernel<<<128, 64>>>(yq, yk, yv);
    // 5) out = xo @ W_proj  (TF32 tensor cores)
    gemm_tf32<<<dim3(CDIM / 128, MTOT / 128), 256, GEMM_SMEM>>>(
        xo_p, W_proj, out, MTOT, CDIM, CDIM);
}